// round 1
// baseline (speedup 1.0000x reference)
#include <cuda_runtime.h>
#include <math.h>

// Problem constants (from reference setup_inputs)
#define BB   16
#define NVV  6890
#define NFF  13776
#define F2   (2 * NFF)     // 27552 triangles per person-pair
#define PP   8             // B/2 person pairs
#define CC   65536         // collisions per pair
#define SIGMA_F  1e-4f
#define EPS_F    1e-9f
#define THRESH_F 2000.0f
#define WEIGHT_F 0.1f

// Scratch (static device arrays — no dynamic allocation)
__device__ float4 g_verts4[BB * NVV];          // padded translated vertices (1.76 MB)
__device__ float4 g_tri[PP * F2 * 3];          // intruder triangle vertices (10.6 MB)
__device__ float4 g_recv[PP * F2 * 2];         // {n.xyz, radius}, {c.xyz, 0}  (7.05 MB)
__device__ double g_pen[PP];

// ---------------------------------------------------------------------------
// Kernel 0: vertices = verts + trans, padded to float4; also zero g_pen.
// ---------------------------------------------------------------------------
__global__ void k0_pad(const float* __restrict__ verts,
                       const float* __restrict__ trans) {
    int i = blockIdx.x * blockDim.x + threadIdx.x;
    if (i < PP) g_pen[i] = 0.0;
    if (i >= BB * NVV) return;
    int b = i / NVV;
    float tx = trans[b * 3 + 0];
    float ty = trans[b * 3 + 1];
    float tz = trans[b * 3 + 2];
    g_verts4[i] = make_float4(verts[3 * i + 0] + tx,
                              verts[3 * i + 1] + ty,
                              verts[3 * i + 2] + tz, 0.0f);
}

// ---------------------------------------------------------------------------
// Kernel 1: per (p, triangle): gather 3 vertices, store intruder payload and
// receiver frame {unit normal, centroid, circumscribed radius}.
// ---------------------------------------------------------------------------
__global__ void k1_tri(const int* __restrict__ faces) {
    int gid = blockIdx.x * blockDim.x + threadIdx.x;
    if (gid >= PP * F2) return;
    int p   = gid / F2;
    int f2  = gid - p * F2;
    int half = (f2 >= NFF) ? 1 : 0;
    int fm  = f2 - half * NFF;
    int person = 2 * p + half;
    int vofs = person * NVV;

    int i0 = faces[fm * 3 + 0] + vofs;
    int i1 = faces[fm * 3 + 1] + vofs;
    int i2 = faces[fm * 3 + 2] + vofs;

    float4 v0 = g_verts4[i0];
    float4 v1 = g_verts4[i1];
    float4 v2 = g_verts4[i2];

    // intruder payload
    g_tri[gid * 3 + 0] = v0;
    g_tri[gid * 3 + 1] = v1;
    g_tri[gid * 3 + 2] = v2;

    // receiver frame
    float e1x = v1.x - v0.x, e1y = v1.y - v0.y, e1z = v1.z - v0.z;
    float e2x = v2.x - v0.x, e2y = v2.y - v0.y, e2z = v2.z - v0.z;
    float nx = e1y * e2z - e1z * e2y;
    float ny = e1z * e2x - e1x * e2z;
    float nz = e1x * e2y - e1y * e2x;
    float nn = sqrtf(nx * nx + ny * ny + nz * nz) + EPS_F;
    nx /= nn; ny /= nn; nz /= nn;

    float cx = (v0.x + v1.x + v2.x) / 3.0f;
    float cy = (v0.y + v1.y + v2.y) / 3.0f;
    float cz = (v0.z + v1.z + v2.z) / 3.0f;

    float d0 = (v0.x - cx) * (v0.x - cx) + (v0.y - cy) * (v0.y - cy) + (v0.z - cz) * (v0.z - cz);
    float d1 = (v1.x - cx) * (v1.x - cx) + (v1.y - cy) * (v1.y - cy) + (v1.z - cz) * (v1.z - cz);
    float d2 = (v2.x - cx) * (v2.x - cx) + (v2.y - cy) * (v2.y - cy) + (v2.z - cz) * (v2.z - cz);
    float radius = sqrtf(fmaxf(d0, fmaxf(d1, d2)));

    g_recv[gid * 2 + 0] = make_float4(nx, ny, nz, radius);
    g_recv[gid * 2 + 1] = make_float4(cx, cy, cz, 0.0f);
}

// ---------------------------------------------------------------------------
// Kernel 2: per collision, evaluate conical distance field at 3 intruder
// vertices; block-reduce (double) and atomicAdd into g_pen[p].
// grid: 2048 blocks x 256 threads; 256 blocks per p.
// ---------------------------------------------------------------------------
__global__ void k2_coll(const int* __restrict__ cidx) {
    int p = blockIdx.x >> 8;
    int c = ((blockIdx.x & 255) << 8) + threadIdx.x;

    int2 pr = *(const int2*)(cidx + ((size_t)(p * CC + c)) * 2);

    float pl = 0.0f;
    if (pr.x != pr.y) {
        int rbase = (p * F2 + pr.y) * 2;
        float4 n4 = g_recv[rbase + 0];
        float4 c4 = g_recv[rbase + 1];
        int ibase = (p * F2 + pr.x) * 3;
        float4 a0 = g_tri[ibase + 0];
        float4 a1 = g_tri[ibase + 1];
        float4 a2 = g_tri[ibase + 2];

        float radius = n4.w + EPS_F;

        #pragma unroll
        for (int v = 0; v < 3; v++) {
            float ax = (v == 0) ? a0.x : (v == 1) ? a1.x : a2.x;
            float ay = (v == 0) ? a0.y : (v == 1) ? a1.y : a2.y;
            float az = (v == 0) ? a0.z : (v == 1) ? a1.z : a2.z;
            float dx = ax - c4.x;
            float dy = ay - c4.y;
            float dz = az - c4.z;
            float d = dx * n4.x + dy * n4.y + dz * n4.z;
            float rx = dx - d * n4.x;
            float ry = dy - d * n4.y;
            float rz = dz - d * n4.z;
            float radial = sqrtf(rx * rx + ry * ry + rz * rz);
            float f = fmaxf(-d / SIGMA_F, 0.0f) * fmaxf(1.0f - radial / radius, 0.0f);
            pl += f * f;
        }
    }

    // warp reduce in double
    double v = (double)pl;
    #pragma unroll
    for (int off = 16; off > 0; off >>= 1)
        v += __shfl_down_sync(0xFFFFFFFFu, v, off);

    __shared__ double ws[8];
    int lane = threadIdx.x & 31;
    int wid  = threadIdx.x >> 5;
    if (lane == 0) ws[wid] = v;
    __syncthreads();
    if (threadIdx.x == 0) {
        double s = 0.0;
        #pragma unroll
        for (int w = 0; w < 8; w++) s += ws[w];
        atomicAdd(&g_pen[p], s);
    }
}

// ---------------------------------------------------------------------------
// Kernel 3: finalize loss.
// ---------------------------------------------------------------------------
__global__ void k3_final(float* __restrict__ out) {
    if (threadIdx.x == 0 && blockIdx.x == 0) {
        float cnt = 0.0f, vsum = 0.0f;
        for (int p = 0; p < PP; p++) {
            float pen = (float)g_pen[p];
            if (pen < THRESH_F) {
                cnt += 1.0f;
                float x = pen / THRESH_F;
                float sig = 1.0f / (1.0f + expf(-x));
                vsum += sig - 0.5f;
            }
        }
        out[0] = (cnt > 0.0f) ? (vsum / cnt) * WEIGHT_F : 0.0f;
    }
}

// ---------------------------------------------------------------------------
extern "C" void kernel_launch(void* const* d_in, const int* in_sizes, int n_in,
                              void* d_out, int out_size) {
    const float* verts = (const float*)d_in[0];
    const float* trans = (const float*)d_in[1];
    const int*   faces = (const int*)d_in[2];
    const int*   cidx  = (const int*)d_in[3];
    float* out = (float*)d_out;

    k0_pad<<<(BB * NVV + 255) / 256, 256>>>(verts, trans);
    k1_tri<<<(PP * F2 + 255) / 256, 256>>>(faces);
    k2_coll<<<2048, 256>>>(cidx);
    k3_final<<<1, 32>>>(out);
}

// round 3
// speedup vs baseline: 1.1778x; 1.1778x over previous
#include <cuda_runtime.h>
#include <cuda_fp16.h>
#include <math.h>

// Problem constants (from reference setup_inputs)
#define BB   16
#define NVV  6890
#define NFF  13776
#define F2   (2 * NFF)     // 27552 triangles per person-pair
#define PP   8             // B/2 person pairs
#define CC   65536         // collisions per pair
#define K2_GRID 2048       // 256 blocks per pair x 8 pairs
#define EPS_F    1e-9f
#define THRESH_F 2000.0f
#define WEIGHT_F 0.1f
#define INV_SIGMA 1e4f

// Scratch (static device arrays — no dynamic allocation)
__device__ float4 g_verts4[BB * NVV];      // padded translated vertices (1.76 MB)
// One 32B record per (pair, triangle): 16 halves
//  h0..h8  : v0.xyz v1.xyz v2.xyz   (intruder payload)
//  h9..h11 : unit normal n
//  h12..h14: centroid c
//  h15     : circumscribed radius
__device__ uint4  g_rec[PP * F2 * 2];      // 7.05 MB, L2-resident
__device__ double g_pen2[64];              // 8 pairs x 8 banks
__device__ unsigned g_done;                // zero-initialized at load

static __device__ __forceinline__ unsigned h2u(__half2 h) {
    return *reinterpret_cast<unsigned*>(&h);
}

// ---------------------------------------------------------------------------
// Kernel 0: vertices = verts + trans, padded to float4; zero accumulators.
// ---------------------------------------------------------------------------
__global__ void k0_pad(const float* __restrict__ verts,
                       const float* __restrict__ trans) {
    int i = blockIdx.x * blockDim.x + threadIdx.x;
    if (i < 64) g_pen2[i] = 0.0;
    if (i == 64) g_done = 0u;
    if (i >= BB * NVV) return;
    int b = i / NVV;
    float tx = trans[b * 3 + 0];
    float ty = trans[b * 3 + 1];
    float tz = trans[b * 3 + 2];
    g_verts4[i] = make_float4(verts[3 * i + 0] + tx,
                              verts[3 * i + 1] + ty,
                              verts[3 * i + 2] + tz, 0.0f);
}

// ---------------------------------------------------------------------------
// Kernel 1: per (p, triangle): gather 3 vertices, build 32B fp16 record
// holding the intruder payload + receiver frame.
// ---------------------------------------------------------------------------
__global__ void k1_tri(const int* __restrict__ faces) {
    int gid = blockIdx.x * blockDim.x + threadIdx.x;
    if (gid >= PP * F2) return;
    int p    = gid / F2;
    int f2   = gid - p * F2;
    int half = (f2 >= NFF) ? 1 : 0;
    int fm   = f2 - half * NFF;
    int vofs = (2 * p + half) * NVV;

    int i0 = faces[fm * 3 + 0] + vofs;
    int i1 = faces[fm * 3 + 1] + vofs;
    int i2 = faces[fm * 3 + 2] + vofs;

    float4 v0 = g_verts4[i0];
    float4 v1 = g_verts4[i1];
    float4 v2 = g_verts4[i2];

    // receiver frame (fp32 math, then quantize)
    float e1x = v1.x - v0.x, e1y = v1.y - v0.y, e1z = v1.z - v0.z;
    float e2x = v2.x - v0.x, e2y = v2.y - v0.y, e2z = v2.z - v0.z;
    float nx = e1y * e2z - e1z * e2y;
    float ny = e1z * e2x - e1x * e2z;
    float nz = e1x * e2y - e1y * e2x;
    float nn = sqrtf(nx * nx + ny * ny + nz * nz) + EPS_F;
    nx /= nn; ny /= nn; nz /= nn;

    float cx = (v0.x + v1.x + v2.x) * (1.0f / 3.0f);
    float cy = (v0.y + v1.y + v2.y) * (1.0f / 3.0f);
    float cz = (v0.z + v1.z + v2.z) * (1.0f / 3.0f);

    float d0 = (v0.x - cx) * (v0.x - cx) + (v0.y - cy) * (v0.y - cy) + (v0.z - cz) * (v0.z - cz);
    float d1 = (v1.x - cx) * (v1.x - cx) + (v1.y - cy) * (v1.y - cy) + (v1.z - cz) * (v1.z - cz);
    float d2 = (v2.x - cx) * (v2.x - cx) + (v2.y - cy) * (v2.y - cy) + (v2.z - cz) * (v2.z - cz);
    float radius = sqrtf(fmaxf(d0, fmaxf(d1, d2)));

    uint4 u0 = make_uint4(
        h2u(__floats2half2_rn(v0.x, v0.y)),
        h2u(__floats2half2_rn(v0.z, v1.x)),
        h2u(__floats2half2_rn(v1.y, v1.z)),
        h2u(__floats2half2_rn(v2.x, v2.y)));
    uint4 u1 = make_uint4(
        h2u(__floats2half2_rn(v2.z, nx)),
        h2u(__floats2half2_rn(ny, nz)),
        h2u(__floats2half2_rn(cx, cy)),
        h2u(__floats2half2_rn(cz, radius)));

    g_rec[gid * 2 + 0] = u0;
    g_rec[gid * 2 + 1] = u1;
}

// ---------------------------------------------------------------------------
// Kernel 2: per collision, evaluate conical distance field at 3 intruder
// vertices; block-reduce; last block finalizes the loss.
// ---------------------------------------------------------------------------
__global__ void __launch_bounds__(256) k2_coll(const int* __restrict__ cidx,
                                               float* __restrict__ out) {
    int p = blockIdx.x >> 8;
    int c = ((blockIdx.x & 255) << 8) + threadIdx.x;

    int2 pr = *(const int2*)(cidx + ((size_t)(p * CC + c)) * 2);

    float pl = 0.0f;
    if (pr.x != pr.y) {
        int base = p * F2;
        const uint4* __restrict__ rec = g_rec;
        uint4 ca = rec[(base + pr.x) * 2 + 0];   // intr halves 0..7
        uint4 cb = rec[(base + pr.x) * 2 + 1];   // intr half 8 (+unused)
        uint4 rb = rec[(base + pr.y) * 2 + 1];   // recv halves 9..15

        float2 t;
        t = __half22float2(*(__half2*)&ca.x); float v0x = t.x, v0y = t.y;
        t = __half22float2(*(__half2*)&ca.y); float v0z = t.x, v1x = t.y;
        t = __half22float2(*(__half2*)&ca.z); float v1y = t.x, v1z = t.y;
        t = __half22float2(*(__half2*)&ca.w); float v2x = t.x, v2y = t.y;
        t = __half22float2(*(__half2*)&cb.x); float v2z = t.x;
        t = __half22float2(*(__half2*)&rb.x); float nx  = t.y;
        t = __half22float2(*(__half2*)&rb.y); float ny  = t.x, nz = t.y;
        t = __half22float2(*(__half2*)&rb.z); float cx  = t.x, cy = t.y;
        t = __half22float2(*(__half2*)&rb.w); float cz  = t.x, rad = t.y;

        float invR = 1.0f / (rad + EPS_F);

        float vx[3] = {v0x, v1x, v2x};
        float vy[3] = {v0y, v1y, v2y};
        float vz[3] = {v0z, v1z, v2z};
        #pragma unroll
        for (int v = 0; v < 3; v++) {
            float dx = vx[v] - cx;
            float dy = vy[v] - cy;
            float dz = vz[v] - cz;
            float d  = dx * nx + dy * ny + dz * nz;
            float rx = dx - d * nx;
            float ry = dy - d * ny;
            float rz = dz - d * nz;
            float radial = sqrtf(rx * rx + ry * ry + rz * rz);
            float f = fmaxf(-d, 0.0f) * INV_SIGMA * fmaxf(1.0f - radial * invR, 0.0f);
            pl += f * f;
        }
    }

    // warp reduce (float), then block reduce, then banked double atomic
    #pragma unroll
    for (int off = 16; off > 0; off >>= 1)
        pl += __shfl_down_sync(0xFFFFFFFFu, pl, off);

    __shared__ float ws[8];
    int lane = threadIdx.x & 31;
    int wid  = threadIdx.x >> 5;
    if (lane == 0) ws[wid] = pl;
    __syncthreads();

    __shared__ bool isLast;
    if (threadIdx.x == 0) {
        float s = 0.0f;
        #pragma unroll
        for (int w = 0; w < 8; w++) s += ws[w];
        atomicAdd(&g_pen2[p * 8 + (blockIdx.x & 7)], (double)s);
        __threadfence();
        unsigned prev = atomicInc(&g_done, K2_GRID - 1);  // wraps to 0 at last block
        isLast = (prev == K2_GRID - 1);
    }
    __syncthreads();

    if (isLast) {
        __shared__ double sp[64];
        if (threadIdx.x < 64)
            sp[threadIdx.x] = *((volatile double*)&g_pen2[threadIdx.x]);
        __syncthreads();
        if (threadIdx.x == 0) {
            float cnt = 0.0f, vsum = 0.0f;
            for (int pp = 0; pp < PP; pp++) {
                double s = 0.0;
                #pragma unroll
                for (int j = 0; j < 8; j++) s += sp[pp * 8 + j];
                float pen = (float)s;
                if (pen < THRESH_F) {
                    cnt += 1.0f;
                    float x = pen / THRESH_F;
                    float sig = 1.0f / (1.0f + expf(-x));
                    vsum += sig - 0.5f;
                }
            }
            out[0] = (cnt > 0.0f) ? (vsum / cnt) * WEIGHT_F : 0.0f;
        }
    }
}

// ---------------------------------------------------------------------------
extern "C" void kernel_launch(void* const* d_in, const int* in_sizes, int n_in,
                              void* d_out, int out_size) {
    const float* verts = (const float*)d_in[0];
    const float* trans = (const float*)d_in[1];
    const int*   faces = (const int*)d_in[2];
    const int*   cidx  = (const int*)d_in[3];
    float* out = (float*)d_out;

    k0_pad<<<(BB * NVV + 255) / 256, 256>>>(verts, trans);
    k1_tri<<<(PP * F2 + 255) / 256, 256>>>(faces);
    k2_coll<<<K2_GRID, 256>>>(cidx, out);
}